// round 12
// baseline (speedup 1.0000x reference)
#include <cuda_runtime.h>
#include <cuda_fp16.h>
#include <cstdint>

// Problem constants
#define CB   2048
#define CT   64
#define CM   256
#define CP   256
#define DSS  520     // sDSh row stride in halves ([d(256) | c(256)] + pad)
#define GPAD 34      // sGate row stride (floats)

// decoder smem layout (float offsets)
#define OFF_SGATE 0        // [512][GPAD] fp32 gates (local half-units) = 17408
#define OFF_SDSH  17408    // [32][DSS] fp16 [d|c] all 28(+4) cluster batches = 8320 floats
#define OFF_SX1H  25728    // [32][256] fp16 x1 (full rows, both halves)  = 4096 floats
#define OFF_SCT   29824    // [14][256] fp32 context (own batches)        = 3584
#define OFF_SL    33408    // [14][64] scores/beta (own batches)          = 896
#define OFF_SYT   34304    // [32] y_tilda (cluster batches)
#define SMEM_FLOATS 34336
#define SMEM_BYTES  (SMEM_FLOATS * 4)   // 137,344 B

// ue_tc smem: [128][280] halves
#define UE_STRIDE 280
#define UE_SMEM_BYTES (128 * UE_STRIDE * 2)

typedef unsigned long long ull;

// ---------------- device scratch ----------------
__device__ __align__(16) __half  g_UeH[(size_t)CB * CT * CM];   // fp16 Ue
__device__ __align__(16) float   g_we[(size_t)CB * CT];         // enc . w_tilda
__device__ __align__(16) uint4   g_WdF2[2 * 8 * 32 * 32];       // Wd  fragments [r][m][kt][lane]
__device__ __align__(16) uint4   g_WhhF2[2 * 32 * 16 * 32];     // Whh fragments [r][T][kt][lane]
__device__ __align__(16) uint2   g_UdF2[32 * 16 * 32];          // Ud  B-fragments [nt][kt][lane]
__device__ float g_bcomb[1024];
__device__ float g_weff[512];
__device__ float g_beff[1];

// ---------------- helpers ----------------
__device__ __forceinline__ ull pack2(float lo, float hi) {
    ull r; asm("mov.b64 %0, {%1, %2};" : "=l"(r) : "f"(lo), "f"(hi)); return r;
}
__device__ __forceinline__ ull bcast2(float x) { return pack2(x, x); }
__device__ __forceinline__ ull fma2(ull a, ull b, ull c) {
    ull d; asm("fma.rn.f32x2 %0, %1, %2, %3;" : "=l"(d) : "l"(a), "l"(b), "l"(c)); return d;
}
__device__ __forceinline__ float2 unpack2(ull v) {
    float2 f; asm("mov.b64 {%0, %1}, %2;" : "=f"(f.x), "=f"(f.y) : "l"(v)); return f;
}
__device__ __forceinline__ float fast_ex2(float x) {
    float y; asm("ex2.approx.f32 %0, %1;" : "=f"(y) : "f"(x)); return y;
}
__device__ __forceinline__ float fast_rcp(float x) {
    float y; asm("rcp.approx.f32 %0, %1;" : "=f"(y) : "f"(x)); return y;
}
__device__ __forceinline__ float tanh_f(float x) {
    float e = fast_ex2(2.8853900817779268f * x);
    return fmaf(-2.f, fast_rcp(e + 1.f), 1.f);
}
__device__ __forceinline__ unsigned tanh_h2(unsigned x) {
    unsigned y; asm("tanh.approx.f16x2 %0, %1;" : "=r"(y) : "r"(x)); return y;
}
__device__ __forceinline__ float sigm_f(float x) {
    float e = fast_ex2(-1.4426950408889634f * x);
    return fast_rcp(1.f + e);
}
__device__ __forceinline__ float wredsum(float s) {
#pragma unroll
    for (int o = 16; o; o >>= 1) s += __shfl_xor_sync(0xffffffffu, s, o);
    return s;
}
__device__ __forceinline__ float wredmax(float s) {
#pragma unroll
    for (int o = 16; o; o >>= 1) s = fmaxf(s, __shfl_xor_sync(0xffffffffu, s, o));
    return s;
}
__device__ __forceinline__ uint32_t smem_u32(const void* p) {
    uint32_t a;
    asm("{ .reg .u64 t; cvta.to.shared.u64 t, %1; cvt.u32.u64 %0, t; }" : "=r"(a) : "l"(p));
    return a;
}
__device__ __forceinline__ uint32_t mapa_peer(uint32_t laddr, uint32_t rank) {
    uint32_t ra;
    asm("mapa.shared::cluster.u32 %0, %1, %2;" : "=r"(ra) : "r"(laddr), "r"(rank));
    return ra;
}
__device__ __forceinline__ void st_cluster_u16(uint32_t addr, unsigned short v) {
    asm volatile("st.shared::cluster.u16 [%0], %1;" :: "r"(addr), "h"(v) : "memory");
}
__device__ __forceinline__ void st_cluster_f32(uint32_t addr, float v) {
    asm volatile("st.shared::cluster.f32 [%0], %1;" :: "r"(addr), "f"(v) : "memory");
}
#define CLUSTER_SYNC() do { \
    asm volatile("barrier.cluster.arrive.aligned;" ::: "memory"); \
    asm volatile("barrier.cluster.wait.aligned;" ::: "memory"); } while (0)

// m16n8k16 row.col f32.f16.f16.f32
__device__ __forceinline__ void mma16816(float* c, uint4 A, uint32_t b0, uint32_t b1) {
    asm volatile("mma.sync.aligned.m16n8k16.row.col.f32.f16.f16.f32 "
        "{%0,%1,%2,%3}, {%4,%5,%6,%7}, {%8,%9}, {%0,%1,%2,%3};"
        : "+f"(c[0]), "+f"(c[1]), "+f"(c[2]), "+f"(c[3])
        : "r"(A.x), "r"(A.y), "r"(A.z), "r"(A.w), "r"(b0), "r"(b1));
}

// ---------------- prep: weight fragments (rank-split) + folded head ----------------
__global__ void prep_kernel(const float* __restrict__ Wd,
                            const float* __restrict__ Whh,
                            const float* __restrict__ Ud,
                            const float* __restrict__ bih,
                            const float* __restrict__ bhh,
                            const float* __restrict__ vy,
                            const float* __restrict__ Wy,
                            const float* __restrict__ Wyb,
                            const float* __restrict__ vyb)
{
    int i = blockIdx.x * blockDim.x + threadIdx.x;
    if (i < 16384) {   // WdF2: [r(2)][m(8)][kt(32)][lane(32)]
        int lane = i & 31, kt = (i >> 5) & 31, m = (i >> 10) & 7, rr = i >> 13;
        int j0 = rr * 128 + m * 16 + (lane >> 2);
        int k0 = kt * 16 + (lane & 3) * 2;
        __half2 a = __floats2half2_rn(Wd[j0 * 512 + k0],       Wd[j0 * 512 + k0 + 1]);
        __half2 b = __floats2half2_rn(Wd[(j0 + 8) * 512 + k0], Wd[(j0 + 8) * 512 + k0 + 1]);
        __half2 c = __floats2half2_rn(Wd[j0 * 512 + k0 + 8],   Wd[j0 * 512 + k0 + 9]);
        __half2 d = __floats2half2_rn(Wd[(j0 + 8) * 512 + k0 + 8], Wd[(j0 + 8) * 512 + k0 + 9]);
        uint4 v;
        v.x = *(uint32_t*)&a; v.y = *(uint32_t*)&b; v.z = *(uint32_t*)&c; v.w = *(uint32_t*)&d;
        g_WdF2[i] = v;
        return;
    }
    i -= 16384;
    if (i < 32768) {   // WhhF2: [r(2)][T(32)][kt(16)][lane(32)]
        int lane = i & 31, kt = (i >> 5) & 15, T = (i >> 9) & 31, rr = i >> 14;
        int gate = T >> 3;
        int j0 = gate * 256 + rr * 128 + (T & 7) * 16 + (lane >> 2);
        int k0 = kt * 16 + (lane & 3) * 2;
        __half2 a = __floats2half2_rn(Whh[j0 * 256 + k0],       Whh[j0 * 256 + k0 + 1]);
        __half2 b = __floats2half2_rn(Whh[(j0 + 8) * 256 + k0], Whh[(j0 + 8) * 256 + k0 + 1]);
        __half2 c = __floats2half2_rn(Whh[j0 * 256 + k0 + 8],   Whh[j0 * 256 + k0 + 9]);
        __half2 d = __floats2half2_rn(Whh[(j0 + 8) * 256 + k0 + 8], Whh[(j0 + 8) * 256 + k0 + 9]);
        uint4 v;
        v.x = *(uint32_t*)&a; v.y = *(uint32_t*)&b; v.z = *(uint32_t*)&c; v.w = *(uint32_t*)&d;
        g_WhhF2[i] = v;
        return;
    }
    i -= 32768;
    if (i < 16384) {   // Ud B-fragments: [nt(32)][kt(16)][lane(32)]
        int lane = i & 31, kt = (i >> 5) & 15, nt = i >> 9;
        int n = nt * 8 + (lane >> 2);
        int k0 = kt * 16 + (lane & 3) * 2;
        __half2 b0 = __floats2half2_rn(Ud[n * 256 + k0],     Ud[n * 256 + k0 + 1]);
        __half2 b1 = __floats2half2_rn(Ud[n * 256 + k0 + 8], Ud[n * 256 + k0 + 9]);
        uint2 v; v.x = *(uint32_t*)&b0; v.y = *(uint32_t*)&b1;
        g_UdF2[i] = v;
        return;
    }
    i -= 16384;
    if (i < 1024) { g_bcomb[i] = bih[i] + bhh[i]; return; }
    i -= 1024;
    if (i < 512) {
        float s = 0.f;
        for (int j = 0; j < 256; ++j) s += vy[j] * Wy[j * 512 + i];
        g_weff[i] = s; return;
    }
    i -= 512;
    if (i == 0) {
        float s = 0.f;
        for (int j = 0; j < 256; ++j) s += vy[j] * Wyb[j];
        g_beff[0] = s + vyb[0];
    }
}

// ---------------- ue_tc: Ue = enc @ Ud^T via HMMA; we = enc.wt ----------------
__global__ __launch_bounds__(256, 2) void ue_tc_kernel(const float* __restrict__ enc,
                                                       const float* __restrict__ wt)
{
    extern __shared__ __align__(16) __half Eh[];   // [128][UE_STRIDE]
    const int tid  = threadIdx.x;
    const int lane = tid & 31;
    const int w    = tid >> 5;
    const int bt0  = blockIdx.x * 128;

    for (int i = tid; i < 8192; i += 256) {
        int r = i >> 6, c4 = i & 63;
        float4 v = ((const float4*)(enc + (size_t)(bt0 + r) * 256))[c4];
        __half2 h0 = __floats2half2_rn(v.x, v.y);
        __half2 h1 = __floats2half2_rn(v.z, v.w);
        *(__half2*)&Eh[r * UE_STRIDE + c4 * 4]     = h0;
        *(__half2*)&Eh[r * UE_STRIDE + c4 * 4 + 2] = h1;
    }
    __syncthreads();

    {
        float2 wtr[4];
#pragma unroll
        for (int i = 0; i < 4; ++i)
            wtr[i] = make_float2(wt[i * 64 + lane * 2], wt[i * 64 + lane * 2 + 1]);
        for (int r = w; r < 128; r += 8) {
            float s = 0.f;
#pragma unroll
            for (int i = 0; i < 4; ++i) {
                float2 f = __half22float2(*(__half2*)&Eh[r * UE_STRIDE + i * 64 + lane * 2]);
                s = fmaf(f.x, wtr[i].x, fmaf(f.y, wtr[i].y, s));
            }
            s = wredsum(s);
            if (lane == 0) g_we[bt0 + r] = s;
        }
    }

    const int r0   = w * 16 + (lane >> 2);
    const int koff = (lane & 3) * 2;
    const int cc   = (lane & 3) * 2;
#pragma unroll
    for (int pass = 0; pass < 2; ++pass) {
        float acc[16][4];
#pragma unroll
        for (int nt = 0; nt < 16; ++nt)
#pragma unroll
            for (int q = 0; q < 4; ++q) acc[nt][q] = 0.f;

        for (int kt = 0; kt < 16; ++kt) {
            uint4 A;
            A.x = *(const uint32_t*)&Eh[r0 * UE_STRIDE + kt * 16 + koff];
            A.y = *(const uint32_t*)&Eh[(r0 + 8) * UE_STRIDE + kt * 16 + koff];
            A.z = *(const uint32_t*)&Eh[r0 * UE_STRIDE + kt * 16 + koff + 8];
            A.w = *(const uint32_t*)&Eh[(r0 + 8) * UE_STRIDE + kt * 16 + koff + 8];
#pragma unroll
            for (int nt = 0; nt < 16; ++nt) {
                uint2 B = g_UdF2[((((pass * 16 + nt) << 4) + kt) << 5) + lane];
                mma16816(acc[nt], A, B.x, B.y);
            }
        }
#pragma unroll
        for (int nt = 0; nt < 16; ++nt) {
            int ncol = ((pass * 16 + nt) << 3) + cc;
            __half2 h01 = __floats2half2_rn(acc[nt][0], acc[nt][1]);
            __half2 h23 = __floats2half2_rn(acc[nt][2], acc[nt][3]);
            *(__half2*)(g_UeH + (size_t)(bt0 + r0) * 256 + ncol)     = h01;
            *(__half2*)(g_UeH + (size_t)(bt0 + r0 + 8) * 256 + ncol) = h23;
        }
    }
}

// ---------------- persistent decoder: 148 CTAs = 74 clusters of 2, 28 batches/cluster ----------------
__global__ __launch_bounds__(512, 1) __cluster_dims__(2, 1, 1)
void decoder_kernel(
    const float* __restrict__ enc,
    const float* __restrict__ yin,
    const float* __restrict__ Wdb, const float* __restrict__ vd,
    const float* __restrict__ wt,  const float* __restrict__ wtb,
    const float* __restrict__ Wih, float* __restrict__ out)
{
    extern __shared__ __align__(16) float sm[];
    float*  sGate = sm + OFF_SGATE;            // [512][GPAD]
    __half* sDSh  = (__half*)(sm + OFF_SDSH);  // [32][DSS]
    __half* sX1h  = (__half*)(sm + OFF_SX1H);  // [32][256]
    float*  sCt   = sm + OFF_SCT;              // [14][256]
    float*  sL    = sm + OFF_SL;               // [14][64]
    float*  sYt   = sm + OFF_SYT;              // [32]

    const int tid  = threadIdx.x;
    const int lane = tid & 31;
    const int wid  = tid >> 5;
    const int r    = blockIdx.x & 1;            // cluster rank
    const int base_b = blockIdx.x * 14;         // global batch base for OWN 14 batches

    const uint32_t smbase = smem_u32(sm);
    const uint32_t pbase  = mapa_peer(smbase, (uint32_t)(r ^ 1));
    const uint32_t pX1h   = pbase + OFF_SX1H * 4;
    const uint32_t pDSh   = pbase + OFF_SDSH * 4;
    const uint32_t pYt    = pbase + OFF_SYT * 4;

    // zero state (sDSh covers all 32 rows incl. pad batches) + sYt
    for (int i = tid; i < 8320; i += 512) ((float*)sDSh)[i] = 0.f;
    if (tid < 32) sYt[tid] = 0.f;

    // cached per-lane vectors
    ull vd2[4];
#pragma unroll
    for (int j = 0; j < 4; ++j)
        vd2[j] = pack2(vd[lane * 8 + 2 * j], vd[lane * 8 + 2 * j + 1]);
    const float wt256 = wt[256];
    const float wtb0  = wtb[0];

    // pointwise constants: local unit uloc, global unit gu
    const int uloc = tid & 127;
    const int gu   = r * 128 + uloc;
    const int quarter = tid >> 7;
    const float bI = g_bcomb[gu],       wI = Wih[gu];
    const float bF = g_bcomb[256 + gu], wF = Wih[256 + gu];
    const float bG = g_bcomb[512 + gu], wG = Wih[512 + gu];
    const float bO = g_bcomb[768 + gu], wO = Wih[768 + gu];
    float creg[7];
#pragma unroll
    for (int j = 0; j < 7; ++j) creg[j] = 0.f;

    // MMA geometry
    const int qrow = lane >> 2;
    const int koff = (lane & 3) * 2;
    const int a_m  = wid >> 1, a_n = wid & 1;
    const int lrowA = a_m * 16 + qrow;               // local x1 row [0,128)
    const float bbA0 = Wdb[r * 128 + lrowA];
    const float bbA1 = Wdb[r * 128 + lrowA + 8];
    const uint4* afA  = g_WdF2  + (((r << 3) + a_m) << 10) + lane;   // [kt<<5]
    const uint4* afE0 = g_WhhF2 + (((r << 5) + wid * 2) << 9) + lane;
    const uint4* afE1 = afE0 + 512;

    __syncthreads();
    CLUSTER_SYNC();

    for (int t = 0; t < CT; ++t) {
        // ---- MMA-A: x1 rows [r*128, +128) for 32 cluster batches ----
        {
            float cA[2][4];
#pragma unroll
            for (int q = 0; q < 2; ++q)
#pragma unroll
                for (int j = 0; j < 4; ++j) cA[q][j] = 0.f;
#pragma unroll 4
            for (int kt = 0; kt < 32; ++kt) {
                uint4 A = afA[kt << 5];
                int k0 = (kt << 4) + koff;
#pragma unroll
                for (int q = 0; q < 2; ++q) {
                    int gc = a_n * 16 + q * 8 + qrow;
                    uint32_t b0 = *(const uint32_t*)(sDSh + gc * DSS + k0);
                    uint32_t b1 = *(const uint32_t*)(sDSh + gc * DSS + k0 + 8);
                    mma16816(cA[q], A, b0, b1);
                }
            }
            int grow = r * 128 + lrowA;
#pragma unroll
            for (int q = 0; q < 2; ++q) {
                int g0 = a_n * 16 + q * 8 + (lane & 3) * 2;
                __half h0 = __float2half_rn(cA[q][0] + bbA0);
                __half h1 = __float2half_rn(cA[q][1] + bbA0);
                __half h2 = __float2half_rn(cA[q][2] + bbA1);
                __half h3 = __float2half_rn(cA[q][3] + bbA1);
                int i0 = g0 * 256 + grow, i1 = i0 + 256;
                sX1h[i0] = h0;      sX1h[i1] = h1;
                sX1h[i0 + 8] = h2;  sX1h[i1 + 8] = h3;
                st_cluster_u16(pX1h + i0 * 2,       __half_as_ushort(h0));
                st_cluster_u16(pX1h + i1 * 2,       __half_as_ushort(h1));
                st_cluster_u16(pX1h + (i0 + 8) * 2, __half_as_ushort(h2));
                st_cluster_u16(pX1h + (i1 + 8) * 2, __half_as_ushort(h3));
            }
        }

        // ---- MMA-E: gates rows (local 512) for 32 cluster batches ----
        {
            float cE[2][4][4];
#pragma unroll
            for (int tt = 0; tt < 2; ++tt)
#pragma unroll
                for (int q = 0; q < 4; ++q)
#pragma unroll
                    for (int j = 0; j < 4; ++j) cE[tt][q][j] = 0.f;
#pragma unroll 2
            for (int kt = 0; kt < 16; ++kt) {
                int k0 = (kt << 4) + koff;
                uint32_t b0[4], b1[4];
#pragma unroll
                for (int q = 0; q < 4; ++q) {
                    int gc = q * 8 + qrow;
                    b0[q] = *(const uint32_t*)(sDSh + gc * DSS + k0);
                    b1[q] = *(const uint32_t*)(sDSh + gc * DSS + k0 + 8);
                }
                uint4 A0 = afE0[kt << 5];
                uint4 A1 = afE1[kt << 5];
#pragma unroll
                for (int q = 0; q < 4; ++q) {
                    mma16816(cE[0][q], A0, b0[q], b1[q]);
                    mma16816(cE[1][q], A1, b0[q], b1[q]);
                }
            }
#pragma unroll
            for (int tt = 0; tt < 2; ++tt) {
                int row = (wid * 2 + tt) * 16 + qrow;
#pragma unroll
                for (int q = 0; q < 4; ++q) {
                    int g0 = q * 8 + (lane & 3) * 2;
                    *(float2*)&sGate[row * GPAD + g0]       = make_float2(cE[tt][q][0], cE[tt][q][1]);
                    *(float2*)&sGate[(row + 8) * GPAD + g0] = make_float2(cE[tt][q][2], cE[tt][q][3]);
                }
            }
        }
        CLUSTER_SYNC();   // x1 halves exchanged; local gates done

        // ---- Phase B: attention scores for OWN 14 batches (4-way interleave) ----
        for (int p0 = wid; p0 < 14 * CT; p0 += 64) {
            uint4 u[4];
#pragma unroll
            for (int j = 0; j < 4; ++j) {
                int p = p0 + 16 * j;
                int b = min(base_b + (p >> 6), CB - 1);
                u[j] = *((const uint4*)(g_UeH + (((size_t)b * CT + (p & 63)) << 8)) + lane);
            }
            float sres[4];
#pragma unroll
            for (int j = 0; j < 4; ++j) {
                int p = p0 + 16 * j;
                int gc = r * 14 + (p >> 6);
                uint4 x = *((const uint4*)(sX1h + (gc << 8)) + lane);
                const __half2* uh = (const __half2*)&u[j];
                const __half2* xh = (const __half2*)&x;
                __half2 s0 = __hadd2(uh[0], xh[0]);
                __half2 s1 = __hadd2(uh[1], xh[1]);
                __half2 s2 = __hadd2(uh[2], xh[2]);
                __half2 s3 = __hadd2(uh[3], xh[3]);
                unsigned z0 = tanh_h2(*(unsigned*)&s0);
                unsigned z1 = tanh_h2(*(unsigned*)&s1);
                unsigned z2 = tanh_h2(*(unsigned*)&s2);
                unsigned z3 = tanh_h2(*(unsigned*)&s3);
                float2 f0 = __half22float2(*(__half2*)&z0);
                float2 f1 = __half22float2(*(__half2*)&z1);
                float2 f2 = __half22float2(*(__half2*)&z2);
                float2 f3 = __half22float2(*(__half2*)&z3);
                ull acc = 0ull;
                acc = fma2(pack2(f0.x, f0.y), vd2[0], acc);
                acc = fma2(pack2(f1.x, f1.y), vd2[1], acc);
                acc = fma2(pack2(f2.x, f2.y), vd2[2], acc);
                acc = fma2(pack2(f3.x, f3.y), vd2[3], acc);
                float2 f = unpack2(acc);
                sres[j] = f.x + f.y;
            }
#pragma unroll
            for (int o = 16; o; o >>= 1) {
#pragma unroll
                for (int j = 0; j < 4; ++j)
                    sres[j] += __shfl_xor_sync(0xffffffffu, sres[j], o);
            }
            if (lane == 0) {
#pragma unroll
                for (int j = 0; j < 4; ++j) sL[p0 + 16 * j] = sres[j];
            }
        }
        __syncthreads();

        // ---- B2: softmax + fused y_tilda (warps 0-13 for own batches) ----
        if (wid < 14) {
            int gl = wid;
            int b = min(base_b + gl, CB - 1);
            float l0 = sL[gl * 64 + lane], l1 = sL[gl * 64 + 32 + lane];
            float mx = wredmax(fmaxf(l0, l1));
            float e0 = fast_ex2((l0 - mx) * 1.4426950408889634f);
            float e1 = fast_ex2((l1 - mx) * 1.4426950408889634f);
            float w0 = g_we[b * CT + lane], w1 = g_we[b * CT + 32 + lane];
            float ps = e0 + e1;
            float pw = fmaf(e0, w0, e1 * w1);
#pragma unroll
            for (int o = 16; o; o >>= 1) {
                ps += __shfl_xor_sync(0xffffffffu, ps, o);
                pw += __shfl_xor_sync(0xffffffffu, pw, o);
            }
            float inv = fast_rcp(ps);
            inv = inv * (2.f - ps * inv);
            sL[gl * 64 + lane]      = e0 * inv;
            sL[gl * 64 + 32 + lane] = e1 * inv;
            if (lane == 0) {
                float yt = yin[b * CT + t];
                float v = fmaf(pw, inv, fmaf(yt, wt256, wtb0));
                int gc = r * 14 + gl;
                sYt[gc] = v;
                st_cluster_f32(pYt + gc * 4, v);
            }
        }
        CLUSTER_SYNC();   // y_tilda exchanged

        // ---- Pointwise: unit gu for 7 cluster batches each ----
        {
#pragma unroll
            for (int j = 0; j < 7; ++j) {
                int g = quarter * 7 + j;
                float yt = sYt[g];
                float iv = sGate[uloc * GPAD + g]         + bI + yt * wI;
                float fv = sGate[(128 + uloc) * GPAD + g] + bF + yt * wF;
                float gv = sGate[(256 + uloc) * GPAD + g] + bG + yt * wG;
                float ov = sGate[(384 + uloc) * GPAD + g] + bO + yt * wO;
                float cn = fmaf(sigm_f(fv), creg[j], sigm_f(iv) * tanh_f(gv));
                creg[j] = cn;
                float h = sigm_f(ov) * tanh_f(cn);
                __half hh = __float2half_rn(h), hc = __float2half_rn(cn);
                int di = g * DSS + gu;
                int ci = di + 256;
                sDSh[di] = hh; sDSh[ci] = hc;
                st_cluster_u16(pDSh + di * 2, __half_as_ushort(hh));
                st_cluster_u16(pDSh + ci * 2, __half_as_ushort(hc));
            }
        }
        CLUSTER_SYNC();   // state exchanged
    }

    // ---- Phase C (once): c_t = beta @ enc (fp32, own batches) ----
    if (wid < 14) {
        int gl = wid;
        int b = min(base_b + gl, CB - 1);
        const float4* ep = (const float4*)(enc + (size_t)b * CT * 256) + lane * 2;
        float4 a0 = make_float4(0.f, 0.f, 0.f, 0.f);
        float4 a1 = make_float4(0.f, 0.f, 0.f, 0.f);
#pragma unroll 4
        for (int tt = 0; tt < 64; ++tt) {
            float bb = sL[gl * 64 + tt];
            float4 e0 = ep[tt * 64];
            float4 e1 = ep[tt * 64 + 1];
            a0.x = fmaf(bb, e0.x, a0.x); a0.y = fmaf(bb, e0.y, a0.y);
            a0.z = fmaf(bb, e0.z, a0.z); a0.w = fmaf(bb, e0.w, a0.w);
            a1.x = fmaf(bb, e1.x, a1.x); a1.y = fmaf(bb, e1.y, a1.y);
            a1.z = fmaf(bb, e1.z, a1.z); a1.w = fmaf(bb, e1.w, a1.w);
        }
        float* cp = sCt + gl * 256 + lane * 8;
        ((float4*)cp)[0] = a0;
        ((float4*)cp)[1] = a1;
    }
    __syncthreads();

    // ---- Final head ----
    if (wid < 14) {
        int gl = wid;
        int gc = r * 14 + gl;
        float s = 0.f;
#pragma unroll
        for (int i = 0; i < 8; ++i) {
            int m = lane + 32 * i;
            s = fmaf(__half2float(sDSh[gc * DSS + m]), g_weff[m], s);
            s = fmaf(sCt[gl * 256 + m], g_weff[256 + m], s);
        }
        s = wredsum(s);
        if (lane == 0 && base_b + gl < CB) out[base_b + gl] = s + g_beff[0];
    }
    for (int p = tid; p < 14 * CT; p += 512) {
        int gl = p >> 6, tt = p & 63;
        if (base_b + gl < CB)
            out[CB + (size_t)(base_b + gl) * CT + tt] = sL[gl * 64 + tt];
    }
    CLUSTER_SYNC();
}

// ---------------- launcher ----------------
extern "C" void kernel_launch(void* const* d_in, const int* in_sizes, int n_in,
                              void* d_out, int out_size)
{
    (void)in_sizes; (void)n_in; (void)out_size;
    const float* enc = (const float*)d_in[0];
    const float* y   = (const float*)d_in[1];
    const float* Wd  = (const float*)d_in[2];
    const float* Wdb = (const float*)d_in[3];
    const float* Ud  = (const float*)d_in[4];
    const float* vd  = (const float*)d_in[5];
    const float* wt  = (const float*)d_in[6];
    const float* wtb = (const float*)d_in[7];
    const float* Wy  = (const float*)d_in[8];
    const float* Wyb = (const float*)d_in[9];
    const float* vy  = (const float*)d_in[10];
    const float* vyb = (const float*)d_in[11];
    const float* Wih = (const float*)d_in[12];
    const float* Whh = (const float*)d_in[13];
    const float* bih = (const float*)d_in[14];
    const float* bhh = (const float*)d_in[15];
    float* out = (float*)d_out;

    cudaFuncSetAttribute(decoder_kernel,
                         cudaFuncAttributeMaxDynamicSharedMemorySize, SMEM_BYTES);
    cudaFuncSetAttribute(ue_tc_kernel,
                         cudaFuncAttributeMaxDynamicSharedMemorySize, UE_SMEM_BYTES);

    // 16384 + 32768 + 16384 + 1024 + 512 + 1 = 67073 threads -> 263 blocks of 256
    prep_kernel<<<263, 256>>>(Wd, Whh, Ud, bih, bhh, vy, Wy, Wyb, vyb);
    ue_tc_kernel<<<1024, 256, UE_SMEM_BYTES>>>(enc, wt);
    decoder_kernel<<<148, 512, SMEM_BYTES>>>(enc, y, Wdb, vd, wt, wtb, Wih, out);
}